// round 1
// baseline (speedup 1.0000x reference)
#include <cuda_runtime.h>
#include <cstdint>

// Problem constants (fixed by the dataset)
#define NTOK 8192     // B*T = 4*2048
#define INF  4096
#define OUTF 4096
#define NEXP 8
#define RANK 16
#define TOPK 2
// SCALING = lora_alpha / r = 16/16 = 1.0

// ---------------- scratch (device globals; no runtime allocation) -----------
__device__ int   g_idx [NTOK * TOPK];                 // selected expert ids
__device__ float g_wts [NTOK * TOPK];                 // softmax weights
__device__ float g_coef[NTOK * TOPK * RANK];          // w_k * (x @ A_e^T)  per token

// ---------------- 1. router: logits -> top2 -> softmax ----------------------
__global__ void __launch_bounds__(256) router_kernel(
    const float* __restrict__ x, const float* __restrict__ Wr)
{
    const int t = blockIdx.x;
    const float* xt = x + (size_t)t * INF;

    float acc[NEXP];
#pragma unroll
    for (int e = 0; e < NEXP; e++) acc[e] = 0.f;

    for (int i = threadIdx.x; i < INF; i += 256) {
        float xv = xt[i];
#pragma unroll
        for (int e = 0; e < NEXP; e++)
            acc[e] += xv * Wr[e * INF + i];
    }
    // warp reduce each accumulator
#pragma unroll
    for (int e = 0; e < NEXP; e++)
#pragma unroll
        for (int off = 16; off > 0; off >>= 1)
            acc[e] += __shfl_down_sync(0xffffffffu, acc[e], off);

    __shared__ float sred[NEXP][8];
    const int warp = threadIdx.x >> 5, lane = threadIdx.x & 31;
    if (lane == 0) {
#pragma unroll
        for (int e = 0; e < NEXP; e++) sred[e][warp] = acc[e];
    }
    __syncthreads();

    if (threadIdx.x == 0) {
        float logit[NEXP];
#pragma unroll
        for (int e = 0; e < NEXP; e++) {
            float s = 0.f;
#pragma unroll
            for (int w = 0; w < 8; w++) s += sred[e][w];
            logit[e] = s;
        }
        // top-2 (strict >, so ties pick the lowest index — matches jax top_k)
        int i0 = 0;
#pragma unroll
        for (int e = 1; e < NEXP; e++) if (logit[e] > logit[i0]) i0 = e;
        int i1 = (i0 == 0) ? 1 : 0;
#pragma unroll
        for (int e = 0; e < NEXP; e++) {
            if (e == i0) continue;
            if (logit[e] > logit[i1]) i1 = e;
        }
        const float v0 = logit[i0], v1 = logit[i1];
        const float e1 = expf(v1 - v0);          // e0 = 1
        const float inv = 1.f / (1.f + e1);
        g_idx[t * 2 + 0] = i0;  g_idx[t * 2 + 1] = i1;
        g_wts[t * 2 + 0] = inv; g_wts[t * 2 + 1] = e1 * inv;
    }
}

// ---------------- 2. LoRA A for the selected experts -------------------------
// coef[t, k, r] = w_k * sum_i x[t,i] * A_w[e_k, r, i]
__global__ void __launch_bounds__(256) loraA_kernel(
    const float* __restrict__ x, const float* __restrict__ Aw)
{
    const int t = blockIdx.x;
    __shared__ float xs[INF];                         // 16 KB
    {
        const float4* src = (const float4*)(x + (size_t)t * INF);
        float4* dst = (float4*)xs;
        for (int i = threadIdx.x; i < INF / 4; i += 256) dst[i] = src[i];
    }
    __syncthreads();

    const int warp = threadIdx.x >> 5, lane = threadIdx.x & 31;
#pragma unroll
    for (int j = 0; j < 4; j++) {
        const int kr = warp * 4 + j;                  // 0..31
        const int kk = kr >> 4;                       // which of top-2
        const int r  = kr & 15;
        const int e  = g_idx[t * 2 + kk];
        const float* arow = Aw + ((size_t)e * RANK + r) * INF;

        float acc = 0.f;
        for (int i = lane * 4; i < INF; i += 32 * 4) {
            float4 xv = *(const float4*)(xs + i);
            float4 av = *(const float4*)(arow + i);
            acc += xv.x * av.x + xv.y * av.y + xv.z * av.z + xv.w * av.w;
        }
#pragma unroll
        for (int off = 16; off > 0; off >>= 1)
            acc += __shfl_down_sync(0xffffffffu, acc, off);
        if (lane == 0)
            g_coef[t * 32 + kr] = acc * g_wts[t * 2 + kk];   // SCALING = 1.0 folded
    }
}

// ---------------- 3. base GEMM: out = x @ W^T + b ----------------------------
// C[8192,4096] = X[8192,4096] * W[4096,4096]^T  (both K-major), fp32 SIMT SGEMM
#define BM 128
#define BN 128
#define BKD 16
#define SPAD 4
__global__ void __launch_bounds__(256) base_gemm_kernel(
    const float* __restrict__ X, const float* __restrict__ W,
    const float* __restrict__ bias, float* __restrict__ out)
{
    __shared__ float As[BKD][BM + SPAD];
    __shared__ float Bs[BKD][BN + SPAD];

    const int mBase = blockIdx.y * BM;
    const int nBase = blockIdx.x * BN;
    const int tid = threadIdx.x;

    // load mapping: 256 threads, each thread 2 rows x 1 float4 per tile half
    const int lRow = tid >> 2;                 // 0..63
    const int lCol = (tid & 3) << 2;           // 0,4,8,12  (k within tile)
    // compute mapping: 16x16 threads, 8x8 micro-tile each
    const int tCol = (tid & 15) << 3;
    const int tRow = (tid >> 4) << 3;

    float acc[8][8];
#pragma unroll
    for (int i = 0; i < 8; i++)
#pragma unroll
        for (int j = 0; j < 8; j++) acc[i][j] = 0.f;

    for (int k0 = 0; k0 < INF; k0 += BKD) {
#pragma unroll
        for (int rr = 0; rr < BM; rr += 64) {
            float4 a = *(const float4*)(X + (size_t)(mBase + lRow + rr) * INF + k0 + lCol);
            As[lCol + 0][lRow + rr] = a.x;
            As[lCol + 1][lRow + rr] = a.y;
            As[lCol + 2][lRow + rr] = a.z;
            As[lCol + 3][lRow + rr] = a.w;
            float4 b = *(const float4*)(W + (size_t)(nBase + lRow + rr) * INF + k0 + lCol);
            Bs[lCol + 0][lRow + rr] = b.x;
            Bs[lCol + 1][lRow + rr] = b.y;
            Bs[lCol + 2][lRow + rr] = b.z;
            Bs[lCol + 3][lRow + rr] = b.w;
        }
        __syncthreads();

#pragma unroll
        for (int kk = 0; kk < BKD; kk++) {
            float af[8], bf[8];
            *(float4*)(af)     = *(const float4*)&As[kk][tRow];
            *(float4*)(af + 4) = *(const float4*)&As[kk][tRow + 4];
            *(float4*)(bf)     = *(const float4*)&Bs[kk][tCol];
            *(float4*)(bf + 4) = *(const float4*)&Bs[kk][tCol + 4];
#pragma unroll
            for (int i = 0; i < 8; i++)
#pragma unroll
                for (int j = 0; j < 8; j++)
                    acc[i][j] += af[i] * bf[j];
        }
        __syncthreads();
    }

    float bb[8];
#pragma unroll
    for (int j = 0; j < 8; j++) bb[j] = bias[nBase + tCol + j];

#pragma unroll
    for (int i = 0; i < 8; i++) {
        float* orow = out + (size_t)(mBase + tRow + i) * OUTF + nBase + tCol;
#pragma unroll
        for (int j = 0; j < 8; j += 4) {
            float4 v;
            v.x = acc[i][j + 0] + bb[j + 0];
            v.y = acc[i][j + 1] + bb[j + 1];
            v.z = acc[i][j + 2] + bb[j + 2];
            v.w = acc[i][j + 3] + bb[j + 3];
            *(float4*)(orow + j) = v;
        }
    }
}

// ---------------- 4. LoRA B apply: out += sum_k coef[t,k,:] . B_w[e_k, o, :] -
__global__ void __launch_bounds__(128) loraB_kernel(
    const float* __restrict__ Bw, float* __restrict__ out)
{
    const int o = blockIdx.x * 128 + threadIdx.x;
    const int tBase = blockIdx.y * 128;

    for (int tt = 0; tt < 128; tt++) {
        const int t = tBase + tt;
        const int e0 = g_idx[t * 2 + 0];
        const int e1 = g_idx[t * 2 + 1];
        const float4* b0 = (const float4*)(Bw + ((size_t)e0 * OUTF + o) * RANK);
        const float4* b1 = (const float4*)(Bw + ((size_t)e1 * OUTF + o) * RANK);
        const float4* c  = (const float4*)(g_coef + t * 32);

        float acc = 0.f;
#pragma unroll
        for (int q = 0; q < 4; q++) {
            float4 bv = b0[q]; float4 cv = c[q];
            acc += bv.x * cv.x + bv.y * cv.y + bv.z * cv.z + bv.w * cv.w;
        }
#pragma unroll
        for (int q = 0; q < 4; q++) {
            float4 bv = b1[q]; float4 cv = c[q + 4];
            acc += bv.x * cv.x + bv.y * cv.y + bv.z * cv.z + bv.w * cv.w;
        }
        out[(size_t)t * OUTF + o] += acc;
    }
}

// ---------------- launch -----------------------------------------------------
extern "C" void kernel_launch(void* const* d_in, const int* in_sizes, int n_in,
                              void* d_out, int out_size)
{
    const float* x   = (const float*)d_in[0];   // [4,2048,4096]
    const float* Wb  = (const float*)d_in[1];   // [4096,4096]
    const float* bb  = (const float*)d_in[2];   // [4096]
    const float* Wr  = (const float*)d_in[3];   // [8,4096]
    const float* Aw  = (const float*)d_in[4];   // [8,16,4096]
    const float* Bw  = (const float*)d_in[5];   // [8,4096,16]
    // d_in[6] = k (fixed 2)
    float* out = (float*)d_out;

    router_kernel<<<NTOK, 256>>>(x, Wr);
    loraA_kernel <<<NTOK, 256>>>(x, Aw);
    base_gemm_kernel<<<dim3(OUTF / BN, NTOK / BM), 256>>>(x, Wb, bb, out);
    loraB_kernel <<<dim3(OUTF / 128, NTOK / 128), 128>>>(Bw, out);
}

// round 3
// speedup vs baseline: 3.4280x; 3.4280x over previous
#include <cuda_runtime.h>
#include <cuda_bf16.h>
#include <cstdint>

// ---------------- problem constants ----------------
#define NTOK 8192
#define INF  4096
#define OUTF 4096
#define NEXP 8
#define RANK 16
// SCALING = 16/16 = 1.0

// ---------------- GEMM config ----------------
#define BM 128
#define BN 128
#define BK 32                  // bf16 per K-chunk
#define KT (INF / BK)          // 128 iterations
#define NSTAGE 3
#define TILE_B   8192          // one 128x32 bf16 tile (packed 64B rows)
#define STAGE_B  (4 * TILE_B)  // Xh, Xl, Wh, Wl
#define SMEM_TOTAL (NSTAGE * STAGE_B)   // 96 KB

// ---------------- scratch (device globals) ----------------
__device__ __nv_bfloat16 g_Xh[(size_t)NTOK * INF];
__device__ __nv_bfloat16 g_Xl[(size_t)NTOK * INF];
__device__ __nv_bfloat16 g_Wh[(size_t)OUTF * INF];
__device__ __nv_bfloat16 g_Wl[(size_t)OUTF * INF];
__device__ int   g_idx [NTOK * 2];
__device__ float g_wts [NTOK * 2];
__device__ float g_coef[NTOK * 2 * RANK];

// ---------------- helpers ----------------
__device__ __forceinline__ uint32_t smem_u32(const void* p) {
    uint32_t a;
    asm("{ .reg .u64 t; cvta.to.shared.u64 t, %1; cvt.u32.u64 %0, t; }" : "=r"(a) : "l"(p));
    return a;
}
// 16B-chunk XOR swizzle inside a 128x32 bf16 tile (64B packed rows)
__device__ __forceinline__ uint32_t swz(uint32_t row, uint32_t kc) {
    return row * 64u + (((kc ^ (row >> 1)) & 3u) << 4);
}
__device__ __forceinline__ void ldsm_x4(uint32_t (&r)[4], uint32_t addr) {
    asm volatile("ldmatrix.sync.aligned.m8n8.x4.shared.b16 {%0,%1,%2,%3}, [%4];"
        : "=r"(r[0]), "=r"(r[1]), "=r"(r[2]), "=r"(r[3]) : "r"(addr));
}
__device__ __forceinline__ void mma_bf16(float (&c)[4], const uint32_t (&a)[4],
                                         uint32_t b0, uint32_t b1) {
    asm volatile("mma.sync.aligned.m16n8k16.row.col.f32.bf16.bf16.f32 "
        "{%0,%1,%2,%3}, {%4,%5,%6,%7}, {%8,%9}, {%0,%1,%2,%3};"
        : "+f"(c[0]), "+f"(c[1]), "+f"(c[2]), "+f"(c[3])
        : "r"(a[0]), "r"(a[1]), "r"(a[2]), "r"(a[3]), "r"(b0), "r"(b1));
}
__device__ __forceinline__ void cp16(uint32_t saddr, const void* gaddr) {
    asm volatile("cp.async.cg.shared.global [%0], [%1], 16;" :: "r"(saddr), "l"(gaddr));
}

// ---------------- 0. fp32 -> bf16 hi/lo split ----------------
__global__ void __launch_bounds__(256) convert_kernel(
    const float* __restrict__ src, __nv_bfloat16* __restrict__ hi,
    __nv_bfloat16* __restrict__ lo, int n4)
{
    int i = blockIdx.x * 256 + threadIdx.x;
    if (i >= n4) return;
    float4 v = ((const float4*)src)[i];
    __nv_bfloat16 h0 = __float2bfloat16(v.x);
    __nv_bfloat16 h1 = __float2bfloat16(v.y);
    __nv_bfloat16 h2 = __float2bfloat16(v.z);
    __nv_bfloat16 h3 = __float2bfloat16(v.w);
    __nv_bfloat16 l0 = __float2bfloat16(v.x - __bfloat162float(h0));
    __nv_bfloat16 l1 = __float2bfloat16(v.y - __bfloat162float(h1));
    __nv_bfloat16 l2 = __float2bfloat16(v.z - __bfloat162float(h2));
    __nv_bfloat16 l3 = __float2bfloat16(v.w - __bfloat162float(h3));
    __nv_bfloat162 H01{h0, h1}, H23{h2, h3}, L01{l0, l1}, L23{l2, l3};
    uint2 H{*(uint32_t*)&H01, *(uint32_t*)&H23};
    uint2 L{*(uint32_t*)&L01, *(uint32_t*)&L23};
    ((uint2*)hi)[i] = H;
    ((uint2*)lo)[i] = L;
}

// ---------------- 1. router ----------------
__global__ void __launch_bounds__(256) router_kernel(
    const float* __restrict__ x, const float* __restrict__ Wr)
{
    const int t = blockIdx.x;
    const float* xt = x + (size_t)t * INF;
    float acc[NEXP];
#pragma unroll
    for (int e = 0; e < NEXP; e++) acc[e] = 0.f;
    for (int i = threadIdx.x; i < INF; i += 256) {
        float xv = xt[i];
#pragma unroll
        for (int e = 0; e < NEXP; e++) acc[e] += xv * Wr[e * INF + i];
    }
#pragma unroll
    for (int e = 0; e < NEXP; e++)
#pragma unroll
        for (int off = 16; off > 0; off >>= 1)
            acc[e] += __shfl_down_sync(0xffffffffu, acc[e], off);

    __shared__ float sred[NEXP][8];
    const int warp = threadIdx.x >> 5, lane = threadIdx.x & 31;
    if (lane == 0)
#pragma unroll
        for (int e = 0; e < NEXP; e++) sred[e][warp] = acc[e];
    __syncthreads();

    if (threadIdx.x == 0) {
        float logit[NEXP];
#pragma unroll
        for (int e = 0; e < NEXP; e++) {
            float s = 0.f;
#pragma unroll
            for (int w = 0; w < 8; w++) s += sred[e][w];
            logit[e] = s;
        }
        int i0 = 0;
#pragma unroll
        for (int e = 1; e < NEXP; e++) if (logit[e] > logit[i0]) i0 = e;
        int i1 = (i0 == 0) ? 1 : 0;
#pragma unroll
        for (int e = 0; e < NEXP; e++) {
            if (e == i0) continue;
            if (logit[e] > logit[i1]) i1 = e;
        }
        const float e1 = expf(logit[i1] - logit[i0]);
        const float inv = 1.f / (1.f + e1);
        g_idx[t * 2 + 0] = i0;  g_idx[t * 2 + 1] = i1;
        g_wts[t * 2 + 0] = inv; g_wts[t * 2 + 1] = e1 * inv;
    }
}

// ---------------- 2. LoRA A (selected experts only) ----------------
__global__ void __launch_bounds__(256) loraA_kernel(
    const float* __restrict__ x, const float* __restrict__ Aw)
{
    const int t = blockIdx.x;
    __shared__ float xs[INF];
    {
        const float4* src = (const float4*)(x + (size_t)t * INF);
        float4* dst = (float4*)xs;
        for (int i = threadIdx.x; i < INF / 4; i += 256) dst[i] = src[i];
    }
    __syncthreads();

    const int warp = threadIdx.x >> 5, lane = threadIdx.x & 31;
#pragma unroll
    for (int j = 0; j < 4; j++) {
        const int kr = warp * 4 + j;
        const int kk = kr >> 4;
        const int r  = kr & 15;
        const int e  = g_idx[t * 2 + kk];
        const float* arow = Aw + ((size_t)e * RANK + r) * INF;
        float acc = 0.f;
        for (int i = lane * 4; i < INF; i += 32 * 4) {
            float4 xv = *(const float4*)(xs + i);
            float4 av = *(const float4*)(arow + i);
            acc += xv.x * av.x + xv.y * av.y + xv.z * av.z + xv.w * av.w;
        }
#pragma unroll
        for (int off = 16; off > 0; off >>= 1)
            acc += __shfl_down_sync(0xffffffffu, acc, off);
        if (lane == 0)
            g_coef[t * 32 + kr] = acc * g_wts[t * 2 + kk];
    }
}

// ---------------- 3. base GEMM via mma.sync bf16 (3-term split) ----------------
__global__ void __launch_bounds__(256, 2) base_gemm_mma(
    const __nv_bfloat16* __restrict__ Xh, const __nv_bfloat16* __restrict__ Xl,
    const __nv_bfloat16* __restrict__ Wh, const __nv_bfloat16* __restrict__ Wl,
    const float* __restrict__ bias, float* __restrict__ out)
{
    extern __shared__ char smem[];
    const uint32_t sb = smem_u32(smem);
    const int tid  = threadIdx.x;
    const int wid  = tid >> 5, lane = tid & 31;
    const int wm   = wid >> 1, wn = wid & 1;          // 4 x 2 warp grid
    const int mBase = blockIdx.y * BM;
    const int nBase = blockIdx.x * BN;

    // per-thread cp.async geometry: kc = tid&3 (16B chunk), rows r0 and r0+64
    const int kc = tid & 3;
    const int r0 = tid >> 2;                          // 0..63
    const uint32_t so_lo = swz(r0, kc);
    const uint32_t so_hi = swz(r0 + 64, kc);
    const __nv_bfloat16* pXh0 = Xh + (size_t)(mBase + r0) * INF + kc * 8;
    const __nv_bfloat16* pXl0 = Xl + (size_t)(mBase + r0) * INF + kc * 8;
    const __nv_bfloat16* pWh0 = Wh + (size_t)(nBase + r0) * INF + kc * 8;
    const __nv_bfloat16* pWl0 = Wl + (size_t)(nBase + r0) * INF + kc * 8;
    const size_t RD = (size_t)64 * INF;               // +64 rows

    float acc[2][8][4];
#pragma unroll
    for (int mt = 0; mt < 2; mt++)
#pragma unroll
        for (int nt = 0; nt < 8; nt++)
#pragma unroll
            for (int q = 0; q < 4; q++) acc[mt][nt][q] = 0.f;

#define ISSUE_LOADS(kt, s) do {                                          \
        const uint32_t stb_ = sb + (uint32_t)(s) * STAGE_B;              \
        const int ko_ = (kt) * BK;                                       \
        cp16(stb_ + 0 * TILE_B + so_lo, pXh0 + ko_);                     \
        cp16(stb_ + 0 * TILE_B + so_hi, pXh0 + RD + ko_);                \
        cp16(stb_ + 1 * TILE_B + so_lo, pXl0 + ko_);                     \
        cp16(stb_ + 1 * TILE_B + so_hi, pXl0 + RD + ko_);                \
        cp16(stb_ + 2 * TILE_B + so_lo, pWh0 + ko_);                     \
        cp16(stb_ + 2 * TILE_B + so_hi, pWh0 + RD + ko_);                \
        cp16(stb_ + 3 * TILE_B + so_lo, pWl0 + ko_);                     \
        cp16(stb_ + 3 * TILE_B + so_hi, pWl0 + RD + ko_);                \
        asm volatile("cp.async.commit_group;" ::: "memory");             \
    } while (0)

    ISSUE_LOADS(0, 0);
    ISSUE_LOADS(1, 1);

    int s = 0;
    for (int kt = 0; kt < KT; kt++) {
        if (kt < KT - 1) asm volatile("cp.async.wait_group 1;" ::: "memory");
        else             asm volatile("cp.async.wait_group 0;" ::: "memory");
        __syncthreads();

        if (kt + 2 < KT) {
            int s2 = s + 2; if (s2 >= NSTAGE) s2 -= NSTAGE;
            ISSUE_LOADS(kt + 2, s2);
        }

        const uint32_t stb = sb + (uint32_t)s * STAGE_B;
#pragma unroll
        for (int ks = 0; ks < 2; ks++) {              // two k16 steps per BK=32
            const uint32_t kc0 = ks * 2 + (lane >> 4);
            uint32_t ah[2][4], al[2][4];
#pragma unroll
            for (int mt = 0; mt < 2; mt++) {
                const uint32_t arow = wm * 32 + mt * 16 + (lane & 15);
                ldsm_x4(ah[mt], stb + 0 * TILE_B + swz(arow, kc0));
                ldsm_x4(al[mt], stb + 1 * TILE_B + swz(arow, kc0));
            }
#pragma unroll
            for (int nt2 = 0; nt2 < 4; nt2++) {
                const uint32_t brow = wn * 64 + nt2 * 16 + (lane & 15);
                uint32_t bh[4], bl[4];
                ldsm_x4(bh, stb + 2 * TILE_B + swz(brow, kc0));
                ldsm_x4(bl, stb + 3 * TILE_B + swz(brow, kc0));
#pragma unroll
                for (int mt = 0; mt < 2; mt++) {
                    mma_bf16(acc[mt][2 * nt2 + 0], ah[mt], bh[0], bh[2]);
                    mma_bf16(acc[mt][2 * nt2 + 1], ah[mt], bh[1], bh[3]);
                    mma_bf16(acc[mt][2 * nt2 + 0], ah[mt], bl[0], bl[2]);
                    mma_bf16(acc[mt][2 * nt2 + 1], ah[mt], bl[1], bl[3]);
                    mma_bf16(acc[mt][2 * nt2 + 0], al[mt], bh[0], bh[2]);
                    mma_bf16(acc[mt][2 * nt2 + 1], al[mt], bh[1], bh[3]);
                }
            }
        }
        s++; if (s == NSTAGE) s = 0;
    }

    // epilogue: acc + bias -> out
#pragma unroll
    for (int mt = 0; mt < 2; mt++) {
        const int r = mBase + wm * 32 + mt * 16 + (lane >> 2);
#pragma unroll
        for (int nt = 0; nt < 8; nt++) {
            const int c = nBase + wn * 64 + nt * 8 + (lane & 3) * 2;
            const float2 bv = *(const float2*)(bias + c);
            float2 v0{acc[mt][nt][0] + bv.x, acc[mt][nt][1] + bv.y};
            float2 v1{acc[mt][nt][2] + bv.x, acc[mt][nt][3] + bv.y};
            *(float2*)(out + (size_t)r * OUTF + c)       = v0;
            *(float2*)(out + (size_t)(r + 8) * OUTF + c) = v1;
        }
    }
}

// ---------------- 4. LoRA B apply ----------------
__global__ void __launch_bounds__(128) loraB_kernel(
    const float* __restrict__ Bw, float* __restrict__ out)
{
    const int o = blockIdx.x * 128 + threadIdx.x;
    const int tBase = blockIdx.y * 128;
    for (int tt = 0; tt < 128; tt++) {
        const int t = tBase + tt;
        const int e0 = g_idx[t * 2 + 0];
        const int e1 = g_idx[t * 2 + 1];
        const float4* b0 = (const float4*)(Bw + ((size_t)e0 * OUTF + o) * RANK);
        const float4* b1 = (const float4*)(Bw + ((size_t)e1 * OUTF + o) * RANK);
        const float4* c  = (const float4*)(g_coef + t * 32);
        float acc = 0.f;
#pragma unroll
        for (int q = 0; q < 4; q++) {
            float4 bv = b0[q]; float4 cv = c[q];
            acc += bv.x * cv.x + bv.y * cv.y + bv.z * cv.z + bv.w * cv.w;
        }
#pragma unroll
        for (int q = 0; q < 4; q++) {
            float4 bv = b1[q]; float4 cv = c[q + 4];
            acc += bv.x * cv.x + bv.y * cv.y + bv.z * cv.z + bv.w * cv.w;
        }
        out[(size_t)t * OUTF + o] += acc;
    }
}

// ---------------- launch ----------------
extern "C" void kernel_launch(void* const* d_in, const int* in_sizes, int n_in,
                              void* d_out, int out_size)
{
    const float* x   = (const float*)d_in[0];
    const float* Wb  = (const float*)d_in[1];
    const float* bb  = (const float*)d_in[2];
    const float* Wr  = (const float*)d_in[3];
    const float* Aw  = (const float*)d_in[4];
    const float* Bw  = (const float*)d_in[5];
    float* out = (float*)d_out;

    void *pXh, *pXl, *pWh, *pWl;
    cudaGetSymbolAddress(&pXh, g_Xh);
    cudaGetSymbolAddress(&pXl, g_Xl);
    cudaGetSymbolAddress(&pWh, g_Wh);
    cudaGetSymbolAddress(&pWl, g_Wl);

    cudaFuncSetAttribute(base_gemm_mma,
                         cudaFuncAttributeMaxDynamicSharedMemorySize, SMEM_TOTAL);

    convert_kernel<<<(NTOK * INF / 4 + 255) / 256, 256>>>(
        x, (__nv_bfloat16*)pXh, (__nv_bfloat16*)pXl, NTOK * INF / 4);
    convert_kernel<<<(OUTF * INF / 4 + 255) / 256, 256>>>(
        Wb, (__nv_bfloat16*)pWh, (__nv_bfloat16*)pWl, OUTF * INF / 4);

    router_kernel<<<NTOK, 256>>>(x, Wr);
    loraA_kernel <<<NTOK, 256>>>(x, Aw);

    base_gemm_mma<<<dim3(OUTF / BN, NTOK / BM), 256, SMEM_TOTAL>>>(
        (const __nv_bfloat16*)pXh, (const __nv_bfloat16*)pXl,
        (const __nv_bfloat16*)pWh, (const __nv_bfloat16*)pWl, bb, out);

    loraB_kernel<<<dim3(OUTF / 128, NTOK / 128), 128>>>(Bw, out);
}

// round 4
// speedup vs baseline: 4.5575x; 1.3295x over previous
#include <cuda_runtime.h>
#include <cuda_fp16.h>
#include <cstdint>

// ---------------- problem constants ----------------
#define NTOK 8192
#define INF  4096
#define OUTF 4096
#define NEXP 8
#define RANK 16
// SCALING = 16/16 = 1.0

// ---------------- GEMM config ----------------
#define BM 128
#define BN 128
#define BK 32                  // fp16 per K-chunk
#define KT (INF / BK)          // 128 iterations
#define NSTAGE 4
#define TILE_B   8192          // one 128x32 fp16 tile (64B packed rows)
#define STAGE_B  (3 * TILE_B)  // Xh, Xl, Wh
#define SMEM_TOTAL (NSTAGE * STAGE_B)   // 96 KB

// ---------------- scratch (device globals) ----------------
__device__ __half g_Xh[(size_t)NTOK * INF];
__device__ __half g_Xl[(size_t)NTOK * INF];
__device__ __half g_Wh[(size_t)OUTF * INF];
__device__ __half g_Ah[(size_t)NEXP * RANK * INF];   // all-expert A, fp16
__device__ float  g_inter[(size_t)NTOK * NEXP * RANK]; // x @ A_all^T
__device__ int    g_idx [NTOK * 2];
__device__ float  g_wts [NTOK * 2];
__device__ float  g_coef[NTOK * 2 * RANK];

// ---------------- helpers ----------------
__device__ __forceinline__ uint32_t smem_u32(const void* p) {
    uint32_t a;
    asm("{ .reg .u64 t; cvta.to.shared.u64 t, %1; cvt.u32.u64 %0, t; }" : "=r"(a) : "l"(p));
    return a;
}
// 16B-chunk XOR swizzle inside a 128x32 fp16 tile (64B packed rows)
__device__ __forceinline__ uint32_t swz(uint32_t row, uint32_t kc) {
    return row * 64u + (((kc ^ (row >> 1)) & 3u) << 4);
}
__device__ __forceinline__ void ldsm_x4(uint32_t (&r)[4], uint32_t addr) {
    asm volatile("ldmatrix.sync.aligned.m8n8.x4.shared.b16 {%0,%1,%2,%3}, [%4];"
        : "=r"(r[0]), "=r"(r[1]), "=r"(r[2]), "=r"(r[3]) : "r"(addr));
}
__device__ __forceinline__ void mma_fp16(float (&c)[4], const uint32_t (&a)[4],
                                         uint32_t b0, uint32_t b1) {
    asm volatile("mma.sync.aligned.m16n8k16.row.col.f32.f16.f16.f32 "
        "{%0,%1,%2,%3}, {%4,%5,%6,%7}, {%8,%9}, {%0,%1,%2,%3};"
        : "+f"(c[0]), "+f"(c[1]), "+f"(c[2]), "+f"(c[3])
        : "r"(a[0]), "r"(a[1]), "r"(a[2]), "r"(a[3]), "r"(b0), "r"(b1));
}
__device__ __forceinline__ void cp16(uint32_t saddr, const void* gaddr) {
    asm volatile("cp.async.cg.shared.global [%0], [%1], 16;" :: "r"(saddr), "l"(gaddr));
}

// ---------------- 0a. fp32 -> fp16 hi/lo split ----------------
__global__ void __launch_bounds__(256) convert2_kernel(
    const float* __restrict__ src, __half* __restrict__ hi,
    __half* __restrict__ lo, int n4)
{
    int i = blockIdx.x * 256 + threadIdx.x;
    if (i >= n4) return;
    float4 v = ((const float4*)src)[i];
    __half h0 = __float2half(v.x), h1 = __float2half(v.y);
    __half h2 = __float2half(v.z), h3 = __float2half(v.w);
    __half l0 = __float2half(v.x - __half2float(h0));
    __half l1 = __float2half(v.y - __half2float(h1));
    __half l2 = __float2half(v.z - __half2float(h2));
    __half l3 = __float2half(v.w - __half2float(h3));
    __half2 H01{h0, h1}, H23{h2, h3}, L01{l0, l1}, L23{l2, l3};
    uint2 H{*(uint32_t*)&H01, *(uint32_t*)&H23};
    uint2 L{*(uint32_t*)&L01, *(uint32_t*)&L23};
    ((uint2*)hi)[i] = H;
    ((uint2*)lo)[i] = L;
}
// ---------------- 0b. fp32 -> fp16 (hi only) ----------------
__global__ void __launch_bounds__(256) convert1_kernel(
    const float* __restrict__ src, __half* __restrict__ hi, int n4)
{
    int i = blockIdx.x * 256 + threadIdx.x;
    if (i >= n4) return;
    float4 v = ((const float4*)src)[i];
    __half2 H01{__float2half(v.x), __float2half(v.y)};
    __half2 H23{__float2half(v.z), __float2half(v.w)};
    uint2 H{*(uint32_t*)&H01, *(uint32_t*)&H23};
    ((uint2*)hi)[i] = H;
}

// ---------------- 1. router ----------------
__global__ void __launch_bounds__(256) router_kernel(
    const float* __restrict__ x, const float* __restrict__ Wr)
{
    const int t = blockIdx.x;
    const float* xt = x + (size_t)t * INF;
    float acc[NEXP];
#pragma unroll
    for (int e = 0; e < NEXP; e++) acc[e] = 0.f;
    for (int i = threadIdx.x; i < INF; i += 256) {
        float xv = xt[i];
#pragma unroll
        for (int e = 0; e < NEXP; e++) acc[e] += xv * Wr[e * INF + i];
    }
#pragma unroll
    for (int e = 0; e < NEXP; e++)
#pragma unroll
        for (int off = 16; off > 0; off >>= 1)
            acc[e] += __shfl_down_sync(0xffffffffu, acc[e], off);

    __shared__ float sred[NEXP][8];
    const int warp = threadIdx.x >> 5, lane = threadIdx.x & 31;
    if (lane == 0)
#pragma unroll
        for (int e = 0; e < NEXP; e++) sred[e][warp] = acc[e];
    __syncthreads();

    if (threadIdx.x == 0) {
        float logit[NEXP];
#pragma unroll
        for (int e = 0; e < NEXP; e++) {
            float s = 0.f;
#pragma unroll
            for (int w = 0; w < 8; w++) s += sred[e][w];
            logit[e] = s;
        }
        int i0 = 0;
#pragma unroll
        for (int e = 1; e < NEXP; e++) if (logit[e] > logit[i0]) i0 = e;
        int i1 = (i0 == 0) ? 1 : 0;
#pragma unroll
        for (int e = 0; e < NEXP; e++) {
            if (e == i0) continue;
            if (logit[e] > logit[i1]) i1 = e;
        }
        const float e1 = expf(logit[i1] - logit[i0]);
        const float inv = 1.f / (1.f + e1);
        g_idx[t * 2 + 0] = i0;  g_idx[t * 2 + 1] = i1;
        g_wts[t * 2 + 0] = inv; g_wts[t * 2 + 1] = e1 * inv;
    }
}

// ---------------- 2. generic fp16 2-term GEMM (mma.sync) ----------------
// out[m, n] = sum_k (Xh+Xl)[m,k] * Wh[n,k]  (+ bias[n] if bias != nullptr)
__global__ void __launch_bounds__(256, 2) gemm_mma(
    const __half* __restrict__ Xh, const __half* __restrict__ Xl,
    const __half* __restrict__ Wh, const float* __restrict__ bias,
    float* __restrict__ out, int ostride)
{
    extern __shared__ __align__(128) char smem[];
    const uint32_t sb = smem_u32(smem);
    const int tid  = threadIdx.x;
    const int wid  = tid >> 5, lane = tid & 31;
    const int wm   = wid >> 1, wn = wid & 1;          // 4 x 2 warp grid
    const int mBase = blockIdx.y * BM;
    const int nBase = blockIdx.x * BN;

    const int kc = tid & 3;
    const int r0 = tid >> 2;                          // 0..63
    const uint32_t so_lo = swz(r0, kc);
    const uint32_t so_hi = swz(r0 + 64, kc);
    const __half* pXh0 = Xh + (size_t)(mBase + r0) * INF + kc * 8;
    const __half* pXl0 = Xl + (size_t)(mBase + r0) * INF + kc * 8;
    const __half* pWh0 = Wh + (size_t)(nBase + r0) * INF + kc * 8;
    const size_t RD = (size_t)64 * INF;

    float acc[2][8][4];
#pragma unroll
    for (int mt = 0; mt < 2; mt++)
#pragma unroll
        for (int nt = 0; nt < 8; nt++)
#pragma unroll
            for (int q = 0; q < 4; q++) acc[mt][nt][q] = 0.f;

#define ISSUE_LOADS(kt, s) do {                                          \
        const uint32_t stb_ = sb + (uint32_t)(s) * STAGE_B;              \
        const int ko_ = (kt) * BK;                                       \
        cp16(stb_ + 0 * TILE_B + so_lo, pXh0 + ko_);                     \
        cp16(stb_ + 0 * TILE_B + so_hi, pXh0 + RD + ko_);                \
        cp16(stb_ + 1 * TILE_B + so_lo, pXl0 + ko_);                     \
        cp16(stb_ + 1 * TILE_B + so_hi, pXl0 + RD + ko_);                \
        cp16(stb_ + 2 * TILE_B + so_lo, pWh0 + ko_);                     \
        cp16(stb_ + 2 * TILE_B + so_hi, pWh0 + RD + ko_);                \
        asm volatile("cp.async.commit_group;" ::: "memory");             \
    } while (0)

    ISSUE_LOADS(0, 0);
    ISSUE_LOADS(1, 1);
    ISSUE_LOADS(2, 2);

    int s = 0;
    for (int kt = 0; kt < KT; kt++) {
        if (kt + 2 < KT)      asm volatile("cp.async.wait_group 2;" ::: "memory");
        else if (kt + 1 < KT) asm volatile("cp.async.wait_group 1;" ::: "memory");
        else                  asm volatile("cp.async.wait_group 0;" ::: "memory");
        __syncthreads();

        if (kt + 3 < KT) {
            int s2 = s + 3; if (s2 >= NSTAGE) s2 -= NSTAGE;
            ISSUE_LOADS(kt + 3, s2);
        }

        const uint32_t stb = sb + (uint32_t)s * STAGE_B;
#pragma unroll
        for (int ks = 0; ks < 2; ks++) {
            const uint32_t kc0 = ks * 2 + (lane >> 4);
            uint32_t ah[2][4], al[2][4];
#pragma unroll
            for (int mt = 0; mt < 2; mt++) {
                const uint32_t arow = wm * 32 + mt * 16 + (lane & 15);
                ldsm_x4(ah[mt], stb + 0 * TILE_B + swz(arow, kc0));
                ldsm_x4(al[mt], stb + 1 * TILE_B + swz(arow, kc0));
            }
#pragma unroll
            for (int nt2 = 0; nt2 < 4; nt2++) {
                const uint32_t brow = wn * 64 + nt2 * 16 + (lane & 15);
                uint32_t bh[4];
                ldsm_x4(bh, stb + 2 * TILE_B + swz(brow, kc0));
#pragma unroll
                for (int mt = 0; mt < 2; mt++) {
                    mma_fp16(acc[mt][2 * nt2 + 0], ah[mt], bh[0], bh[2]);
                    mma_fp16(acc[mt][2 * nt2 + 1], ah[mt], bh[1], bh[3]);
                    mma_fp16(acc[mt][2 * nt2 + 0], al[mt], bh[0], bh[2]);
                    mma_fp16(acc[mt][2 * nt2 + 1], al[mt], bh[1], bh[3]);
                }
            }
        }
        s++; if (s == NSTAGE) s = 0;
    }

    // epilogue
#pragma unroll
    for (int mt = 0; mt < 2; mt++) {
        const int r = mBase + wm * 32 + mt * 16 + (lane >> 2);
#pragma unroll
        for (int nt = 0; nt < 8; nt++) {
            const int c = nBase + wn * 64 + nt * 8 + (lane & 3) * 2;
            float2 bv{0.f, 0.f};
            if (bias) bv = *(const float2*)(bias + c);
            float2 v0{acc[mt][nt][0] + bv.x, acc[mt][nt][1] + bv.y};
            float2 v1{acc[mt][nt][2] + bv.x, acc[mt][nt][3] + bv.y};
            *(float2*)(out + (size_t)r * ostride + c)       = v0;
            *(float2*)(out + (size_t)(r + 8) * ostride + c) = v1;
        }
    }
}

// ---------------- 3. gather top-k intermediate -> weighted coef ----------------
__global__ void __launch_bounds__(256) gather_kernel()
{
    const int gi = blockIdx.x * 256 + threadIdx.x;   // over NTOK*32
    if (gi >= NTOK * 32) return;
    const int t  = gi >> 5;
    const int kr = gi & 31;
    const int kk = kr >> 4;
    const int r  = kr & 15;
    const int e  = g_idx[t * 2 + kk];
    g_coef[gi] = g_inter[(size_t)t * (NEXP * RANK) + e * RANK + r] * g_wts[t * 2 + kk];
}

// ---------------- 4. LoRA B apply ----------------
__global__ void __launch_bounds__(128) loraB_kernel(
    const float* __restrict__ Bw, float* __restrict__ out)
{
    const int o = blockIdx.x * 128 + threadIdx.x;
    const int tBase = blockIdx.y * 128;
    for (int tt = 0; tt < 128; tt++) {
        const int t = tBase + tt;
        const int e0 = g_idx[t * 2 + 0];
        const int e1 = g_idx[t * 2 + 1];
        const float4* b0 = (const float4*)(Bw + ((size_t)e0 * OUTF + o) * RANK);
        const float4* b1 = (const float4*)(Bw + ((size_t)e1 * OUTF + o) * RANK);
        const float4* c  = (const float4*)(g_coef + t * 32);
        float acc = 0.f;
#pragma unroll
        for (int q = 0; q < 4; q++) {
            float4 bv = b0[q]; float4 cv = c[q];
            acc += bv.x * cv.x + bv.y * cv.y + bv.z * cv.z + bv.w * cv.w;
        }
#pragma unroll
        for (int q = 0; q < 4; q++) {
            float4 bv = b1[q]; float4 cv = c[q + 4];
            acc += bv.x * cv.x + bv.y * cv.y + bv.z * cv.z + bv.w * cv.w;
        }
        out[(size_t)t * OUTF + o] += acc;
    }
}

// ---------------- launch ----------------
extern "C" void kernel_launch(void* const* d_in, const int* in_sizes, int n_in,
                              void* d_out, int out_size)
{
    const float* x   = (const float*)d_in[0];
    const float* Wb  = (const float*)d_in[1];
    const float* bb  = (const float*)d_in[2];
    const float* Wr  = (const float*)d_in[3];
    const float* Aw  = (const float*)d_in[4];
    const float* Bw  = (const float*)d_in[5];
    float* out = (float*)d_out;

    void *pXh, *pXl, *pWh, *pAh, *pInter;
    cudaGetSymbolAddress(&pXh, g_Xh);
    cudaGetSymbolAddress(&pXl, g_Xl);
    cudaGetSymbolAddress(&pWh, g_Wh);
    cudaGetSymbolAddress(&pAh, g_Ah);
    cudaGetSymbolAddress(&pInter, g_inter);

    cudaFuncSetAttribute(gemm_mma,
                         cudaFuncAttributeMaxDynamicSharedMemorySize, SMEM_TOTAL);

    // converts
    convert2_kernel<<<(NTOK * INF / 4 + 255) / 256, 256>>>(
        x, (__half*)pXh, (__half*)pXl, NTOK * INF / 4);
    convert1_kernel<<<(OUTF * INF / 4 + 255) / 256, 256>>>(
        Wb, (__half*)pWh, OUTF * INF / 4);
    convert1_kernel<<<(NEXP * RANK * INF / 4 + 255) / 256, 256>>>(
        Aw, (__half*)pAh, NEXP * RANK * INF / 4);

    // router
    router_kernel<<<NTOK, 256>>>(x, Wr);

    // LoRA A as skinny GEMM over all experts: inter = X @ A_all^T
    gemm_mma<<<dim3(1, NTOK / BM), 256, SMEM_TOTAL>>>(
        (const __half*)pXh, (const __half*)pXl, (const __half*)pAh,
        nullptr, (float*)pInter, NEXP * RANK);

    // gather + weight
    gather_kernel<<<(NTOK * 32 + 255) / 256, 256>>>();

    // base GEMM
    gemm_mma<<<dim3(OUTF / BN, NTOK / BM), 256, SMEM_TOTAL>>>(
        (const __half*)pXh, (const __half*)pXl, (const __half*)pWh,
        bb, out, OUTF);

    // LoRA B
    loraB_kernel<<<dim3(OUTF / 128, NTOK / 128), 128>>>(Bw, out);
}

// round 5
// speedup vs baseline: 6.8700x; 1.5074x over previous
#include <cuda_runtime.h>
#include <cuda_fp16.h>
#include <cstdint>

// ---------------- problem constants ----------------
#define NTOK 8192
#define INF  4096
#define OUTF 4096
#define NEXP 8
#define RANK 16
// SCALING = 16/16 = 1.0

// ---------------- GEMM config ----------------
#define BM 128
#define BN 128
#define BK 32                  // fp16 per K-chunk
#define KT (INF / BK)          // 128 iterations
#define NSTAGE 4
#define TILE_B   8192          // one 128x32 fp16 tile (64B packed rows)
#define STAGE_B  (2 * TILE_B)  // Xh, Wh
#define SMEM_TOTAL (NSTAGE * STAGE_B)   // 64 KB

// ---------------- scratch (device globals) ----------------
__device__ __half g_Xh[(size_t)NTOK * INF];
__device__ __half g_Wh[(size_t)OUTF * INF];
__device__ __half g_Ah[(size_t)NEXP * RANK * INF];     // all-expert A, fp16
__device__ float  g_inter[(size_t)NTOK * NEXP * RANK]; // x @ A_all^T
__device__ int    g_idx [NTOK * 2];
__device__ float  g_wts [NTOK * 2];
__device__ float  g_coef[NTOK * 2 * RANK];

// ---------------- helpers ----------------
__device__ __forceinline__ uint32_t smem_u32(const void* p) {
    uint32_t a;
    asm("{ .reg .u64 t; cvta.to.shared.u64 t, %1; cvt.u32.u64 %0, t; }" : "=r"(a) : "l"(p));
    return a;
}
// 16B-chunk XOR swizzle inside a 128x32 fp16 tile (64B packed rows)
__device__ __forceinline__ uint32_t swz(uint32_t row, uint32_t kc) {
    return row * 64u + (((kc ^ (row >> 1)) & 3u) << 4);
}
__device__ __forceinline__ void ldsm_x4(uint32_t (&r)[4], uint32_t addr) {
    asm volatile("ldmatrix.sync.aligned.m8n8.x4.shared.b16 {%0,%1,%2,%3}, [%4];"
        : "=r"(r[0]), "=r"(r[1]), "=r"(r[2]), "=r"(r[3]) : "r"(addr));
}
__device__ __forceinline__ void mma_fp16(float (&c)[4], const uint32_t (&a)[4],
                                         uint32_t b0, uint32_t b1) {
    asm volatile("mma.sync.aligned.m16n8k16.row.col.f32.f16.f16.f32 "
        "{%0,%1,%2,%3}, {%4,%5,%6,%7}, {%8,%9}, {%0,%1,%2,%3};"
        : "+f"(c[0]), "+f"(c[1]), "+f"(c[2]), "+f"(c[3])
        : "r"(a[0]), "r"(a[1]), "r"(a[2]), "r"(a[3]), "r"(b0), "r"(b1));
}
__device__ __forceinline__ void cp16(uint32_t saddr, const void* gaddr) {
    asm volatile("cp.async.cg.shared.global [%0], [%1], 16;" :: "r"(saddr), "l"(gaddr));
}

// ---------------- 0. fp32 -> fp16 ----------------
__global__ void __launch_bounds__(256) convert1_kernel(
    const float* __restrict__ src, __half* __restrict__ hi, int n4)
{
    int i = blockIdx.x * 256 + threadIdx.x;
    if (i >= n4) return;
    float4 v = ((const float4*)src)[i];
    __half2 H01{__float2half(v.x), __float2half(v.y)};
    __half2 H23{__float2half(v.z), __float2half(v.w)};
    uint2 H{*(uint32_t*)&H01, *(uint32_t*)&H23};
    ((uint2*)hi)[i] = H;
}

// ---------------- 1. router (float4-vectorized) ----------------
__global__ void __launch_bounds__(256) router_kernel(
    const float* __restrict__ x, const float* __restrict__ Wr)
{
    const int t = blockIdx.x;
    const float4* xt = (const float4*)(x + (size_t)t * INF);
    const float4* wr = (const float4*)Wr;

    float acc[NEXP];
#pragma unroll
    for (int e = 0; e < NEXP; e++) acc[e] = 0.f;
#pragma unroll 4
    for (int i = threadIdx.x; i < INF / 4; i += 256) {
        float4 xv = xt[i];
#pragma unroll
        for (int e = 0; e < NEXP; e++) {
            float4 wv = wr[e * (INF / 4) + i];
            acc[e] += xv.x * wv.x + xv.y * wv.y + xv.z * wv.z + xv.w * wv.w;
        }
    }
#pragma unroll
    for (int e = 0; e < NEXP; e++)
#pragma unroll
        for (int off = 16; off > 0; off >>= 1)
            acc[e] += __shfl_down_sync(0xffffffffu, acc[e], off);

    __shared__ float sred[NEXP][8];
    const int warp = threadIdx.x >> 5, lane = threadIdx.x & 31;
    if (lane == 0)
#pragma unroll
        for (int e = 0; e < NEXP; e++) sred[e][warp] = acc[e];
    __syncthreads();

    if (threadIdx.x == 0) {
        float logit[NEXP];
#pragma unroll
        for (int e = 0; e < NEXP; e++) {
            float s = 0.f;
#pragma unroll
            for (int w = 0; w < 8; w++) s += sred[e][w];
            logit[e] = s;
        }
        int i0 = 0;
#pragma unroll
        for (int e = 1; e < NEXP; e++) if (logit[e] > logit[i0]) i0 = e;
        int i1 = (i0 == 0) ? 1 : 0;
#pragma unroll
        for (int e = 0; e < NEXP; e++) {
            if (e == i0) continue;
            if (logit[e] > logit[i1]) i1 = e;
        }
        const float e1 = expf(logit[i1] - logit[i0]);
        const float inv = 1.f / (1.f + e1);
        g_idx[t * 2 + 0] = i0;  g_idx[t * 2 + 1] = i1;
        g_wts[t * 2 + 0] = inv; g_wts[t * 2 + 1] = e1 * inv;
    }
}

// ---------------- 2. fp16 GEMM (mma.sync, single term) ----------------
// out[m, n] = sum_k Xh[m,k] * Wh[n,k]  (+ bias[n] if bias != nullptr)
__global__ void __launch_bounds__(256, 2) gemm_mma(
    const __half* __restrict__ Xh, const __half* __restrict__ Wh,
    const float* __restrict__ bias, float* __restrict__ out, int ostride)
{
    extern __shared__ __align__(128) char smem[];
    const uint32_t sb = smem_u32(smem);
    const int tid  = threadIdx.x;
    const int wid  = tid >> 5, lane = tid & 31;
    const int wm   = wid >> 1, wn = wid & 1;          // 4 x 2 warp grid
    const int mBase = blockIdx.y * BM;
    const int nBase = blockIdx.x * BN;

    const int kc = tid & 3;
    const int r0 = tid >> 2;                          // 0..63
    const uint32_t so_lo = swz(r0, kc);
    const uint32_t so_hi = swz(r0 + 64, kc);
    const __half* pXh0 = Xh + (size_t)(mBase + r0) * INF + kc * 8;
    const __half* pWh0 = Wh + (size_t)(nBase + r0) * INF + kc * 8;
    const size_t RD = (size_t)64 * INF;

    float acc[2][8][4];
#pragma unroll
    for (int mt = 0; mt < 2; mt++)
#pragma unroll
        for (int nt = 0; nt < 8; nt++)
#pragma unroll
            for (int q = 0; q < 4; q++) acc[mt][nt][q] = 0.f;

#define ISSUE_LOADS(kt, s) do {                                          \
        const uint32_t stb_ = sb + (uint32_t)(s) * STAGE_B;              \
        const int ko_ = (kt) * BK;                                       \
        cp16(stb_ + 0 * TILE_B + so_lo, pXh0 + ko_);                     \
        cp16(stb_ + 0 * TILE_B + so_hi, pXh0 + RD + ko_);                \
        cp16(stb_ + 1 * TILE_B + so_lo, pWh0 + ko_);                     \
        cp16(stb_ + 1 * TILE_B + so_hi, pWh0 + RD + ko_);                \
        asm volatile("cp.async.commit_group;" ::: "memory");             \
    } while (0)

    ISSUE_LOADS(0, 0);
    ISSUE_LOADS(1, 1);
    ISSUE_LOADS(2, 2);

    int s = 0;
    for (int kt = 0; kt < KT; kt++) {
        if (kt + 2 < KT)      asm volatile("cp.async.wait_group 2;" ::: "memory");
        else if (kt + 1 < KT) asm volatile("cp.async.wait_group 1;" ::: "memory");
        else                  asm volatile("cp.async.wait_group 0;" ::: "memory");
        __syncthreads();

        if (kt + 3 < KT) {
            int s2 = s + 3; if (s2 >= NSTAGE) s2 -= NSTAGE;
            ISSUE_LOADS(kt + 3, s2);
        }

        const uint32_t stb = sb + (uint32_t)s * STAGE_B;
#pragma unroll
        for (int ks = 0; ks < 2; ks++) {
            const uint32_t kc0 = ks * 2 + (lane >> 4);
            uint32_t ah[2][4];
#pragma unroll
            for (int mt = 0; mt < 2; mt++) {
                const uint32_t arow = wm * 32 + mt * 16 + (lane & 15);
                ldsm_x4(ah[mt], stb + 0 * TILE_B + swz(arow, kc0));
            }
#pragma unroll
            for (int nt2 = 0; nt2 < 4; nt2++) {
                const uint32_t brow = wn * 64 + nt2 * 16 + (lane & 15);
                uint32_t bh[4];
                ldsm_x4(bh, stb + 1 * TILE_B + swz(brow, kc0));
#pragma unroll
                for (int mt = 0; mt < 2; mt++) {
                    mma_fp16(acc[mt][2 * nt2 + 0], ah[mt], bh[0], bh[2]);
                    mma_fp16(acc[mt][2 * nt2 + 1], ah[mt], bh[1], bh[3]);
                }
            }
        }
        s++; if (s == NSTAGE) s = 0;
    }

    // epilogue
#pragma unroll
    for (int mt = 0; mt < 2; mt++) {
        const int r = mBase + wm * 32 + mt * 16 + (lane >> 2);
#pragma unroll
        for (int nt = 0; nt < 8; nt++) {
            const int c = nBase + wn * 64 + nt * 8 + (lane & 3) * 2;
            float2 bv{0.f, 0.f};
            if (bias) bv = *(const float2*)(bias + c);
            float2 v0{acc[mt][nt][0] + bv.x, acc[mt][nt][1] + bv.y};
            float2 v1{acc[mt][nt][2] + bv.x, acc[mt][nt][3] + bv.y};
            *(float2*)(out + (size_t)r * ostride + c)       = v0;
            *(float2*)(out + (size_t)(r + 8) * ostride + c) = v1;
        }
    }
}

// ---------------- 3. gather top-k intermediate -> weighted coef ----------------
__global__ void __launch_bounds__(256) gather_kernel()
{
    const int gi = blockIdx.x * 256 + threadIdx.x;   // over NTOK*32
    if (gi >= NTOK * 32) return;
    const int t  = gi >> 5;
    const int kr = gi & 31;
    const int kk = kr >> 4;
    const int r  = kr & 15;
    const int e  = g_idx[t * 2 + kk];
    g_coef[gi] = g_inter[(size_t)t * (NEXP * RANK) + e * RANK + r] * g_wts[t * 2 + kk];
}

// ---------------- 4. LoRA B apply ----------------
__global__ void __launch_bounds__(128) loraB_kernel(
    const float* __restrict__ Bw, float* __restrict__ out)
{
    const int o = blockIdx.x * 128 + threadIdx.x;
    const int tBase = blockIdx.y * 128;
    for (int tt = 0; tt < 128; tt++) {
        const int t = tBase + tt;
        const int e0 = g_idx[t * 2 + 0];
        const int e1 = g_idx[t * 2 + 1];
        const float4* b0 = (const float4*)(Bw + ((size_t)e0 * OUTF + o) * RANK);
        const float4* b1 = (const float4*)(Bw + ((size_t)e1 * OUTF + o) * RANK);
        const float4* c  = (const float4*)(g_coef + t * 32);
        float acc = 0.f;
#pragma unroll
        for (int q = 0; q < 4; q++) {
            float4 bv = b0[q]; float4 cv = c[q];
            acc += bv.x * cv.x + bv.y * cv.y + bv.z * cv.z + bv.w * cv.w;
        }
#pragma unroll
        for (int q = 0; q < 4; q++) {
            float4 bv = b1[q]; float4 cv = c[q + 4];
            acc += bv.x * cv.x + bv.y * cv.y + bv.z * cv.z + bv.w * cv.w;
        }
        out[(size_t)t * OUTF + o] += acc;
    }
}

// ---------------- launch ----------------
extern "C" void kernel_launch(void* const* d_in, const int* in_sizes, int n_in,
                              void* d_out, int out_size)
{
    const float* x   = (const float*)d_in[0];
    const float* Wb  = (const float*)d_in[1];
    const float* bb  = (const float*)d_in[2];
    const float* Wr  = (const float*)d_in[3];
    const float* Aw  = (const float*)d_in[4];
    const float* Bw  = (const float*)d_in[5];
    float* out = (float*)d_out;

    void *pXh, *pWh, *pAh, *pInter;
    cudaGetSymbolAddress(&pXh, g_Xh);
    cudaGetSymbolAddress(&pWh, g_Wh);
    cudaGetSymbolAddress(&pAh, g_Ah);
    cudaGetSymbolAddress(&pInter, g_inter);

    cudaFuncSetAttribute(gemm_mma,
                         cudaFuncAttributeMaxDynamicSharedMemorySize, SMEM_TOTAL);

    // converts (all hi-only fp16)
    convert1_kernel<<<(NTOK * INF / 4 + 255) / 256, 256>>>(
        x, (__half*)pXh, NTOK * INF / 4);
    convert1_kernel<<<(OUTF * INF / 4 + 255) / 256, 256>>>(
        Wb, (__half*)pWh, OUTF * INF / 4);
    convert1_kernel<<<(NEXP * RANK * INF / 4 + 255) / 256, 256>>>(
        Aw, (__half*)pAh, NEXP * RANK * INF / 4);

    // router
    router_kernel<<<NTOK, 256>>>(x, Wr);

    // LoRA A as skinny GEMM over all experts: inter = X @ A_all^T
    gemm_mma<<<dim3(1, NTOK / BM), 256, SMEM_TOTAL>>>(
        (const __half*)pXh, (const __half*)pAh,
        nullptr, (float*)pInter, NEXP * RANK);

    // gather + weight
    gather_kernel<<<(NTOK * 32 + 255) / 256, 256>>>();

    // base GEMM
    gemm_mma<<<dim3(OUTF / BN, NTOK / BM), 256, SMEM_TOTAL>>>(
        (const __half*)pXh, (const __half*)pWh, bb, out, OUTF);

    // LoRA B
    loraB_kernel<<<dim3(OUTF / 128, NTOK / 128), 128>>>(Bw, out);
}